// round 10
// baseline (speedup 1.0000x reference)
#include <cuda_runtime.h>
#include <math.h>

#define S_LEN    4096
#define LC       16
#define CHAR_DIM 64
#define CHAR_H   128
#define N_DIM    256
#define NH       512
#define N_TAG    64
#define FEAT     384      // N_DIM + CHAR_H
#define G4       2048     // 4*NH
#define NB_WORD  64       // CTAs in persistent word-recurrence kernel

typedef unsigned long long ull;

// ---------------- scratch (static device globals; no allocation) ----------------
__device__ float g_charH0[S_LEN * CHAR_H];
__device__ float g_charH1[S_LEN * CHAR_H];
__device__ float g_charC [S_LEN * CHAR_H];
__device__ float g_Gin   [S_LEN * G4];   // word-LSTM input preactivations (+biases)
__device__ ull   g_hx    [S_LEN * NH];   // packed per-step h: (epoch<<32)|float_bits(h)

// fast gate math: tanh.approx (1 MUFU); sigmoid via 0.5*tanh(0.5x)+0.5
__device__ __forceinline__ float tanha(float x)
{
    float r;
    asm("tanh.approx.f32 %0, %1;" : "=f"(r) : "f"(x));
    return r;
}
__device__ __forceinline__ float sigf(float x)
{
    return fmaf(0.5f, tanha(0.5f * x), 0.5f);
}

// packed f32x2 helpers (FFMA2 is PTX-only; ptxas never auto-fuses)
__device__ __forceinline__ ull fma2(ull a, ull b, ull c)
{
    ull d;
    asm("fma.rn.f32x2 %0, %1, %2, %3;" : "=l"(d) : "l"(a), "l"(b), "l"(c));
    return d;
}
__device__ __forceinline__ ull pk2(float lo, float hi)
{
    ull d;
    asm("mov.b64 %0, {%1, %2};" : "=l"(d) : "f"(lo), "f"(hi));
    return d;
}
__device__ __forceinline__ ull pk2b(unsigned lo, unsigned hi)
{
    ull d;
    asm("mov.b64 %0, {%1, %2};" : "=l"(d) : "r"(lo), "r"(hi));
    return d;
}
__device__ __forceinline__ void upk2(float& lo, float& hi, ull v)
{
    asm("mov.b64 {%0, %1}, %2;" : "=f"(lo), "=f"(hi) : "l"(v));
}

// ---------------- init: zero recurrent state + packed h epochs ----------------
__global__ void k_init()
{
    int i = blockIdx.x * blockDim.x + threadIdx.x;
    int stride = gridDim.x * blockDim.x;
    for (int j = i; j < S_LEN * CHAR_H; j += stride) {
        g_charH0[j] = 0.f;
        g_charC[j]  = 0.f;
    }
    for (size_t j = i; j < (size_t)S_LEN * NH; j += stride) g_hx[j] = 0ull;
}

// ---------------- char LSTM: one time step, fused GEMM + gates ----------------
__global__ void __launch_bounds__(256, 4) k_char_step(
                            const float* __restrict__ ce,
                            const float* __restrict__ Wih,
                            const float* __restrict__ Whh,
                            const float* __restrict__ bih,
                            const float* __restrict__ bhh,
                            const int*   __restrict__ chars,
                            const int*   __restrict__ lens,
                            int t)
{
    __shared__ float As[32 * 65];
    __shared__ float Bs[32 * 65];
    __shared__ float Gs[64 * 65];
    __shared__ int   cidx[64];

    const int w0  = blockIdx.x * 64;
    const int hh0 = blockIdx.y * 16;
    const int tid = threadIdx.x;

    const float* Hin  = (t & 1) ? g_charH1 : g_charH0;
    float*       Hout = (t & 1) ? g_charH0 : g_charH1;

    if (tid < 64) cidx[tid] = chars[(w0 + tid) * LC + t];
    __syncthreads();

    const int ty = tid >> 4, tx = tid & 15;
    float acc[4][4];
#pragma unroll
    for (int i = 0; i < 4; i++)
#pragma unroll
        for (int j = 0; j < 4; j++) acc[i][j] = 0.f;

    for (int k0 = 0; k0 < 192; k0 += 32) {
#pragma unroll
        for (int e = tid; e < 2048; e += 256) {
            const int k = e & 31, q = e >> 5;
            const int kg = k0 + k;
            float av, bv;
            if (kg < CHAR_DIM) av = ce[cidx[q] * CHAR_DIM + kg];
            else               av = Hin[(w0 + q) * CHAR_H + (kg - CHAR_DIM)];
            const int col = (q >> 4) * CHAR_H + hh0 + (q & 15);
            if (kg < CHAR_DIM) bv = Wih[col * CHAR_DIM + kg];
            else               bv = Whh[col * CHAR_H + (kg - CHAR_DIM)];
            As[k * 65 + q] = av;
            Bs[k * 65 + q] = bv;
        }
        __syncthreads();
#pragma unroll
        for (int kk = 0; kk < 32; kk++) {
            float a[4], bb[4];
#pragma unroll
            for (int i = 0; i < 4; i++) a[i]  = As[kk * 65 + ty * 4 + i];
#pragma unroll
            for (int j = 0; j < 4; j++) bb[j] = Bs[kk * 65 + tx * 4 + j];
#pragma unroll
            for (int i = 0; i < 4; i++)
#pragma unroll
                for (int j = 0; j < 4; j++) acc[i][j] = fmaf(a[i], bb[j], acc[i][j]);
        }
        __syncthreads();
    }

#pragma unroll
    for (int i = 0; i < 4; i++)
#pragma unroll
        for (int j = 0; j < 4; j++) Gs[(ty * 4 + i) * 65 + tx * 4 + j] = acc[i][j];
    __syncthreads();

    for (int it = tid; it < 1024; it += 256) {
        const int wi = it >> 4, hi = it & 15;
        const int w = w0 + wi, hh = hh0 + hi;
        float gi = Gs[wi * 65 + hi]      + bih[hh]              + bhh[hh];
        float gf = Gs[wi * 65 + 16 + hi] + bih[CHAR_H + hh]     + bhh[CHAR_H + hh];
        float gg = Gs[wi * 65 + 32 + hi] + bih[2 * CHAR_H + hh] + bhh[2 * CHAR_H + hh];
        float go = Gs[wi * 65 + 48 + hi] + bih[3 * CHAR_H + hh] + bhh[3 * CHAR_H + hh];
        float c_old = g_charC[w * CHAR_H + hh];
        float h_old = Hin[w * CHAR_H + hh];
        float cn = sigf(gf) * c_old + sigf(gi) * tanha(gg);
        float hn = sigf(go) * tanha(cn);
        if (t < lens[w]) {
            g_charC[w * CHAR_H + hh] = cn;
            Hout[w * CHAR_H + hh]    = hn;
        } else {
            Hout[w * CHAR_H + hh]    = h_old;
        }
    }
}

// ---------------- word-LSTM input preactivations: Gin = feat @ Wih^T + bih + bhh ----
__global__ void __launch_bounds__(256, 4) k_gin(
                      const float* __restrict__ wemb,
                      const float* __restrict__ Wih,
                      const float* __restrict__ bih,
                      const float* __restrict__ bhh,
                      const int*   __restrict__ x)
{
    __shared__ float As[32 * 65];
    __shared__ float Bs[32 * 65];
    __shared__ int   widx[64];

    const int w0 = blockIdx.x * 64;
    const int n0 = blockIdx.y * 64;
    const int tid = threadIdx.x;

    if (tid < 64) widx[tid] = x[w0 + tid];
    __syncthreads();

    const int ty = tid >> 4, tx = tid & 15;
    float acc[4][4];
#pragma unroll
    for (int i = 0; i < 4; i++)
#pragma unroll
        for (int j = 0; j < 4; j++) acc[i][j] = 0.f;

    for (int k0 = 0; k0 < FEAT; k0 += 32) {
#pragma unroll
        for (int e = tid; e < 2048; e += 256) {
            const int k = e & 31, q = e >> 5;
            const int kg = k0 + k;
            float av;
            if (kg < N_DIM) av = wemb[widx[q] * N_DIM + kg];
            else            av = g_charH0[(w0 + q) * CHAR_H + (kg - N_DIM)];
            As[k * 65 + q] = av;
            Bs[k * 65 + q] = Wih[(n0 + q) * FEAT + kg];
        }
        __syncthreads();
#pragma unroll
        for (int kk = 0; kk < 32; kk++) {
            float a[4], bb[4];
#pragma unroll
            for (int i = 0; i < 4; i++) a[i]  = As[kk * 65 + ty * 4 + i];
#pragma unroll
            for (int j = 0; j < 4; j++) bb[j] = Bs[kk * 65 + tx * 4 + j];
#pragma unroll
            for (int i = 0; i < 4; i++)
#pragma unroll
                for (int j = 0; j < 4; j++) acc[i][j] = fmaf(a[i], bb[j], acc[i][j]);
        }
        __syncthreads();
    }

#pragma unroll
    for (int i = 0; i < 4; i++) {
        const int w = w0 + ty * 4 + i;
#pragma unroll
        for (int j = 0; j < 4; j++) {
            const int n = n0 + tx * 4 + j;
            g_Gin[w * G4 + n] = acc[i][j] + bih[n] + bhh[n];
        }
    }
}

// ---------------- word-LSTM recurrence: persistent, warp-per-dim, epoch-tagged h ----
// CTA b owns dims b*8..b*8+7; warp wid handles dim d = b*8+wid entirely.
// Lanes: gate g = lane>>3, k-sub = lane&7. Weights in registers (f32x2-packed).
// h published as one atomic STG.64 of (epoch<<32)|h_bits -> NO fence, NO flags,
// NO __syncthreads in the loop; warps are fully decoupled. Readers volatile-load
// h[t-1] pairs, OR-reduce epoch mismatch, retry batch until all epochs == t.
__global__ void __launch_bounds__(256, 1) k_word(const float* __restrict__ Whh)
{
    const int b    = blockIdx.x;
    const int tid  = threadIdx.x;
    const int wid  = tid >> 5;
    const int lane = tid & 31;
    const int sub  = lane & 7;
    const int g    = lane >> 3;
    const int d    = b * 8 + wid;
    const int row  = g * NH + d;

    // thread's 64 weights (k = i*32 + sub*4 + j), packed into 32 f32x2
    ull w2[32];
    {
        const float4* wp = (const float4*)(Whh + (size_t)row * NH);
#pragma unroll
        for (int i = 0; i < 16; i++) {
            float4 v = wp[i * 8 + sub];
            w2[2 * i]     = pk2(v.x, v.y);
            w2[2 * i + 1] = pk2(v.z, v.w);
        }
    }

    float c = 0.f;   // cell state; only lane 0's copy is meaningful

    for (int t = 0; t < S_LEN; t++) {
        float ginv = 0.f;
        if (sub == 0) ginv = g_Gin[t * G4 + row];
        float p = 0.f;
        if (t > 0) {
            const ull* hp = g_hx + (size_t)(t - 1) * NH + sub * 4;
            const unsigned te = (unsigned)t;
            ull a0, a1;
            unsigned bad;
            do {
                a0 = 0ull; a1 = 0ull; bad = 0u;
#pragma unroll
                for (int i = 0; i < 16; i++) {
                    ull q0, q1, q2, q3;
                    asm volatile("ld.volatile.global.v2.u64 {%0,%1}, [%2];"
                                 : "=l"(q0), "=l"(q1) : "l"(hp + i * 32));
                    asm volatile("ld.volatile.global.v2.u64 {%0,%1}, [%2];"
                                 : "=l"(q2), "=l"(q3) : "l"(hp + i * 32 + 2));
                    bad |= ((unsigned)(q0 >> 32) ^ te) | ((unsigned)(q1 >> 32) ^ te)
                         | ((unsigned)(q2 >> 32) ^ te) | ((unsigned)(q3 >> 32) ^ te);
                    a0 = fma2(w2[2 * i],     pk2b((unsigned)q0, (unsigned)q1), a0);
                    a1 = fma2(w2[2 * i + 1], pk2b((unsigned)q2, (unsigned)q3), a1);
                }
            } while (bad != 0u);
            float l0, h0, l1, h1;
            upk2(l0, h0, a0);
            upk2(l1, h1, a1);
            p = (l0 + h0) + (l1 + h1);
        }
        // reduce 8 k-sub lanes within each gate group
        p += __shfl_down_sync(0xffffffffu, p, 4, 8);
        p += __shfl_down_sync(0xffffffffu, p, 2, 8);
        p += __shfl_down_sync(0xffffffffu, p, 1, 8);
        float v = p + ginv;                 // lane0:gi lane8:gf lane16:gg lane24:go
        float gf = __shfl_sync(0xffffffffu, v, 8);
        float gg = __shfl_sync(0xffffffffu, v, 16);
        float go = __shfl_sync(0xffffffffu, v, 24);
        // gate math on all lanes (only lane 0's result is used/stored)
        float cn = sigf(gf) * c + sigf(v) * tanha(gg);
        c = cn;
        float hn = sigf(go) * tanha(cn);
        if (lane == 0) {
            ull pkt = ((ull)(unsigned)(t + 1) << 32) | (ull)__float_as_uint(hn);
            asm volatile("st.volatile.global.u64 [%0], %1;"
                         :: "l"(g_hx + (size_t)t * NH + d), "l"(pkt));
        }
    }
}

// ---------------- logits + log_softmax ----------------
__global__ void k_logits(const float* __restrict__ W1,
                         const float* __restrict__ b1,
                         float* __restrict__ out)
{
    __shared__ float hsh[NH];
    __shared__ float sv[N_TAG];
    const int w = blockIdx.x;
    const int n = threadIdx.x;

    for (int k = n; k < NH; k += N_TAG)
        hsh[k] = __uint_as_float((unsigned)g_hx[(size_t)w * NH + k]);
    __syncthreads();

    const float4* wr = (const float4*)(W1 + n * NH);
    float acc = b1[n];
#pragma unroll 8
    for (int k4 = 0; k4 < NH / 4; k4++) {
        float4 v = wr[k4];
        acc += v.x * hsh[k4 * 4]     + v.y * hsh[k4 * 4 + 1]
             + v.z * hsh[k4 * 4 + 2] + v.w * hsh[k4 * 4 + 3];
    }
    sv[n] = acc;
    __syncthreads();
    float mx = -1e30f;
    for (int i = 0; i < N_TAG; i++) mx = fmaxf(mx, sv[i]);
    float se = 0.f;
    for (int i = 0; i < N_TAG; i++) se += expf(sv[i] - mx);
    out[w * N_TAG + n] = acc - mx - logf(se);
}

// ---------------- launch ----------------
extern "C" void kernel_launch(void* const* d_in, const int* in_sizes, int n_in,
                              void* d_out, int out_size)
{
    const float* char_emb = (const float*)d_in[0];
    const float* char_Wih = (const float*)d_in[1];
    const float* char_Whh = (const float*)d_in[2];
    const float* char_bih = (const float*)d_in[3];
    const float* char_bhh = (const float*)d_in[4];
    const float* word_emb = (const float*)d_in[5];
    const float* Wih      = (const float*)d_in[6];
    const float* Whh      = (const float*)d_in[7];
    const float* bih      = (const float*)d_in[8];
    const float* bhh      = (const float*)d_in[9];
    const float* W1       = (const float*)d_in[10];
    const float* b1       = (const float*)d_in[11];
    const int*   x        = (const int*)d_in[12];
    const int*   chars    = (const int*)d_in[13];
    const int*   lens     = (const int*)d_in[14];
    float* out = (float*)d_out;

    k_init<<<1024, 256>>>();
    for (int t = 0; t < LC; t++)
        k_char_step<<<dim3(64, 8), 256>>>(char_emb, char_Wih, char_Whh,
                                          char_bih, char_bhh, chars, lens, t);
    k_gin<<<dim3(64, 32), 256>>>(word_emb, Wih, bih, bhh, x);
    k_word<<<NB_WORD, 256>>>(Whh);
    k_logits<<<S_LEN, N_TAG>>>(W1, b1, out);
}

// round 15
// speedup vs baseline: 1.8077x; 1.8077x over previous
#include <cuda_runtime.h>
#include <math.h>

#define S_LEN    4096
#define LC       16
#define CHAR_DIM 64
#define CHAR_H   128
#define N_DIM    256
#define NH       512
#define N_TAG    64
#define FEAT     384      // N_DIM + CHAR_H
#define G4       2048     // 4*NH
#define NB_WORD  64       // CTAs in persistent word-recurrence kernel

typedef unsigned long long ull;

// ---------------- scratch (static device globals; no allocation) ----------------
__device__ float g_charH0[S_LEN * CHAR_H];
__device__ float g_charH1[S_LEN * CHAR_H];
__device__ float g_charC [S_LEN * CHAR_H];
__device__ float g_Gin   [S_LEN * G4];   // word-LSTM input preactivations (+biases)
__device__ ull   g_hx    [S_LEN * NH];   // packed per-step h: (epoch<<32)|float_bits(h)

// fast gate math: tanh.approx (1 MUFU); sigmoid via 0.5*tanh(0.5x)+0.5
__device__ __forceinline__ float tanha(float x)
{
    float r;
    asm("tanh.approx.f32 %0, %1;" : "=f"(r) : "f"(x));
    return r;
}
__device__ __forceinline__ float sigf(float x)
{
    return fmaf(0.5f, tanha(0.5f * x), 0.5f);
}

// packed f32x2 helpers (FFMA2 is PTX-only; ptxas never auto-fuses)
__device__ __forceinline__ ull fma2(ull a, ull b, ull c)
{
    ull d;
    asm("fma.rn.f32x2 %0, %1, %2, %3;" : "=l"(d) : "l"(a), "l"(b), "l"(c));
    return d;
}
__device__ __forceinline__ ull pk2(float lo, float hi)
{
    ull d;
    asm("mov.b64 %0, {%1, %2};" : "=l"(d) : "f"(lo), "f"(hi));
    return d;
}
__device__ __forceinline__ void upk2(float& lo, float& hi, ull v)
{
    asm("mov.b64 {%0, %1}, %2;" : "=f"(lo), "=f"(hi) : "l"(v));
}

// ---------------- init: zero recurrent state + packed h epochs ----------------
__global__ void k_init()
{
    int i = blockIdx.x * blockDim.x + threadIdx.x;
    int stride = gridDim.x * blockDim.x;
    for (int j = i; j < S_LEN * CHAR_H; j += stride) {
        g_charH0[j] = 0.f;
        g_charC[j]  = 0.f;
    }
    for (size_t j = i; j < (size_t)S_LEN * NH; j += stride) g_hx[j] = 0ull;
}

// ---------------- char LSTM: one time step, fused GEMM + gates ----------------
__global__ void __launch_bounds__(256, 4) k_char_step(
                            const float* __restrict__ ce,
                            const float* __restrict__ Wih,
                            const float* __restrict__ Whh,
                            const float* __restrict__ bih,
                            const float* __restrict__ bhh,
                            const int*   __restrict__ chars,
                            const int*   __restrict__ lens,
                            int t)
{
    __shared__ float As[32 * 65];
    __shared__ float Bs[32 * 65];
    __shared__ float Gs[64 * 65];
    __shared__ int   cidx[64];

    const int w0  = blockIdx.x * 64;
    const int hh0 = blockIdx.y * 16;
    const int tid = threadIdx.x;

    const float* Hin  = (t & 1) ? g_charH1 : g_charH0;
    float*       Hout = (t & 1) ? g_charH0 : g_charH1;

    if (tid < 64) cidx[tid] = chars[(w0 + tid) * LC + t];
    __syncthreads();

    const int ty = tid >> 4, tx = tid & 15;
    float acc[4][4];
#pragma unroll
    for (int i = 0; i < 4; i++)
#pragma unroll
        for (int j = 0; j < 4; j++) acc[i][j] = 0.f;

    for (int k0 = 0; k0 < 192; k0 += 32) {
#pragma unroll
        for (int e = tid; e < 2048; e += 256) {
            const int k = e & 31, q = e >> 5;
            const int kg = k0 + k;
            float av, bv;
            if (kg < CHAR_DIM) av = ce[cidx[q] * CHAR_DIM + kg];
            else               av = Hin[(w0 + q) * CHAR_H + (kg - CHAR_DIM)];
            const int col = (q >> 4) * CHAR_H + hh0 + (q & 15);
            if (kg < CHAR_DIM) bv = Wih[col * CHAR_DIM + kg];
            else               bv = Whh[col * CHAR_H + (kg - CHAR_DIM)];
            As[k * 65 + q] = av;
            Bs[k * 65 + q] = bv;
        }
        __syncthreads();
#pragma unroll
        for (int kk = 0; kk < 32; kk++) {
            float a[4], bb[4];
#pragma unroll
            for (int i = 0; i < 4; i++) a[i]  = As[kk * 65 + ty * 4 + i];
#pragma unroll
            for (int j = 0; j < 4; j++) bb[j] = Bs[kk * 65 + tx * 4 + j];
#pragma unroll
            for (int i = 0; i < 4; i++)
#pragma unroll
                for (int j = 0; j < 4; j++) acc[i][j] = fmaf(a[i], bb[j], acc[i][j]);
        }
        __syncthreads();
    }

#pragma unroll
    for (int i = 0; i < 4; i++)
#pragma unroll
        for (int j = 0; j < 4; j++) Gs[(ty * 4 + i) * 65 + tx * 4 + j] = acc[i][j];
    __syncthreads();

    for (int it = tid; it < 1024; it += 256) {
        const int wi = it >> 4, hi = it & 15;
        const int w = w0 + wi, hh = hh0 + hi;
        float gi = Gs[wi * 65 + hi]      + bih[hh]              + bhh[hh];
        float gf = Gs[wi * 65 + 16 + hi] + bih[CHAR_H + hh]     + bhh[CHAR_H + hh];
        float gg = Gs[wi * 65 + 32 + hi] + bih[2 * CHAR_H + hh] + bhh[2 * CHAR_H + hh];
        float go = Gs[wi * 65 + 48 + hi] + bih[3 * CHAR_H + hh] + bhh[3 * CHAR_H + hh];
        float c_old = g_charC[w * CHAR_H + hh];
        float h_old = Hin[w * CHAR_H + hh];
        float cn = sigf(gf) * c_old + sigf(gi) * tanha(gg);
        float hn = sigf(go) * tanha(cn);
        if (t < lens[w]) {
            g_charC[w * CHAR_H + hh] = cn;
            Hout[w * CHAR_H + hh]    = hn;
        } else {
            Hout[w * CHAR_H + hh]    = h_old;
        }
    }
}

// ---------------- word-LSTM input preactivations: Gin = feat @ Wih^T + bih + bhh ----
__global__ void __launch_bounds__(256, 4) k_gin(
                      const float* __restrict__ wemb,
                      const float* __restrict__ Wih,
                      const float* __restrict__ bih,
                      const float* __restrict__ bhh,
                      const int*   __restrict__ x)
{
    __shared__ float As[32 * 65];
    __shared__ float Bs[32 * 65];
    __shared__ int   widx[64];

    const int w0 = blockIdx.x * 64;
    const int n0 = blockIdx.y * 64;
    const int tid = threadIdx.x;

    if (tid < 64) widx[tid] = x[w0 + tid];
    __syncthreads();

    const int ty = tid >> 4, tx = tid & 15;
    float acc[4][4];
#pragma unroll
    for (int i = 0; i < 4; i++)
#pragma unroll
        for (int j = 0; j < 4; j++) acc[i][j] = 0.f;

    for (int k0 = 0; k0 < FEAT; k0 += 32) {
#pragma unroll
        for (int e = tid; e < 2048; e += 256) {
            const int k = e & 31, q = e >> 5;
            const int kg = k0 + k;
            float av;
            if (kg < N_DIM) av = wemb[widx[q] * N_DIM + kg];
            else            av = g_charH0[(w0 + q) * CHAR_H + (kg - N_DIM)];
            As[k * 65 + q] = av;
            Bs[k * 65 + q] = Wih[(n0 + q) * FEAT + kg];
        }
        __syncthreads();
#pragma unroll
        for (int kk = 0; kk < 32; kk++) {
            float a[4], bb[4];
#pragma unroll
            for (int i = 0; i < 4; i++) a[i]  = As[kk * 65 + ty * 4 + i];
#pragma unroll
            for (int j = 0; j < 4; j++) bb[j] = Bs[kk * 65 + tx * 4 + j];
#pragma unroll
            for (int i = 0; i < 4; i++)
#pragma unroll
                for (int j = 0; j < 4; j++) acc[i][j] = fmaf(a[i], bb[j], acc[i][j]);
        }
        __syncthreads();
    }

#pragma unroll
    for (int i = 0; i < 4; i++) {
        const int w = w0 + ty * 4 + i;
#pragma unroll
        for (int j = 0; j < 4; j++) {
            const int n = n0 + tx * 4 + j;
            g_Gin[w * G4 + n] = acc[i][j] + bih[n] + bhh[n];
        }
    }
}

// ---------------- word-LSTM recurrence --------------------------------------
// 64 CTAs x 288 threads (9 warps). Warps 0-7: compute, warp-per-dim
// (d = b*8 + wid), weights register-resident as packed f32x2; h read from a
// double-buffered smem stage via conflict-free LDS.128. Warp 8: fetch warp —
// polls the 512 epoch-tagged packed h words of step t-1 (32 lanes x 8
// ld.volatile.v2.u64), strips epochs into smem. One __syncthreads per step
// joins them. Producers publish h as a single st.volatile.global.u64 of
// (t+1)<<32 | h_bits: no fence, no flags, no atomics anywhere in the loop.
__global__ void __launch_bounds__(288, 1) k_word(const float* __restrict__ Whh)
{
    __shared__ float sbuf[2][NH];

    const int b    = blockIdx.x;
    const int tid  = threadIdx.x;
    const int wid  = tid >> 5;
    const int lane = tid & 31;

    if (wid < 8) {
        // ---------- compute warp: owns dim d entirely ----------
        const int sub = lane & 7;       // k-subchunk 0..7
        const int g   = lane >> 3;      // gate 0..3
        const int d   = b * 8 + wid;
        const int row = g * NH + d;

        // thread's 64 weights (k = i*32 + sub*4 + j), packed into 32 f32x2
        ull w2[32];
        {
            const float4* wp = (const float4*)(Whh + (size_t)row * NH);
#pragma unroll
            for (int i = 0; i < 16; i++) {
                float4 v = wp[i * 8 + sub];
                w2[2 * i]     = pk2(v.x, v.y);
                w2[2 * i + 1] = pk2(v.z, v.w);
            }
        }
        float c = 0.f;

        for (int t = 0; t < S_LEN; t++) {
            float ginv = 0.f;
            if (sub == 0) ginv = g_Gin[t * G4 + row];   // prefetch before barrier
            __syncthreads();                            // h[t-1] staged in sbuf
            float p = 0.f;
            if (t > 0) {
                const float4* hp4 = (const float4*)sbuf[(t - 1) & 1];
                ull a0 = 0ull, a1 = 0ull;
#pragma unroll
                for (int i = 0; i < 16; i++) {
                    float4 hv = hp4[i * 8 + sub];
                    a0 = fma2(w2[2 * i],     pk2(hv.x, hv.y), a0);
                    a1 = fma2(w2[2 * i + 1], pk2(hv.z, hv.w), a1);
                }
                float l0, h0, l1, h1;
                upk2(l0, h0, a0);
                upk2(l1, h1, a1);
                p = (l0 + h0) + (l1 + h1);
            }
            // reduce 8 k-sub lanes within each gate group
            p += __shfl_down_sync(0xffffffffu, p, 4, 8);
            p += __shfl_down_sync(0xffffffffu, p, 2, 8);
            p += __shfl_down_sync(0xffffffffu, p, 1, 8);
            float v = p + ginv;             // lane0:gi lane8:gf lane16:gg lane24:go
            float gf = __shfl_sync(0xffffffffu, v, 8);
            float gg = __shfl_sync(0xffffffffu, v, 16);
            float go = __shfl_sync(0xffffffffu, v, 24);
            float cn = sigf(gf) * c + sigf(v) * tanha(gg);
            c = cn;
            float hn = sigf(go) * tanha(cn);
            if (lane == 0) {
                ull pkt = ((ull)(unsigned)(t + 1) << 32) | (ull)__float_as_uint(hn);
                asm volatile("st.volatile.global.u64 [%0], %1;"
                             :: "l"(g_hx + (size_t)t * NH + d), "l"(pkt));
            }
        }
    } else {
        // ---------- fetch warp: stage h[t-1] into smem ----------
        for (int t = 0; t < S_LEN; t++) {
            if (t > 0) {
                const ull* src = g_hx + (size_t)(t - 1) * NH + lane * 16;
                const unsigned te = (unsigned)t;   // h[t-1] carries epoch t
                ull q[16];
                unsigned bad;
                do {
                    bad = 0u;
#pragma unroll
                    for (int i = 0; i < 8; i++) {
                        ull qa, qb;
                        asm volatile("ld.volatile.global.v2.u64 {%0,%1}, [%2];"
                                     : "=l"(qa), "=l"(qb) : "l"(src + 2 * i));
                        q[2 * i]     = qa;
                        q[2 * i + 1] = qb;
                        bad |= ((unsigned)(qa >> 32) ^ te)
                             | ((unsigned)(qb >> 32) ^ te);
                    }
                } while (bad != 0u);
                float4* dst = (float4*)(sbuf[(t - 1) & 1] + lane * 16);
#pragma unroll
                for (int i = 0; i < 4; i++) {
                    float4 fv;
                    fv.x = __uint_as_float((unsigned)q[4 * i]);
                    fv.y = __uint_as_float((unsigned)q[4 * i + 1]);
                    fv.z = __uint_as_float((unsigned)q[4 * i + 2]);
                    fv.w = __uint_as_float((unsigned)q[4 * i + 3]);
                    dst[i] = fv;
                }
            }
            __syncthreads();
        }
    }
}

// ---------------- logits + log_softmax ----------------
__global__ void k_logits(const float* __restrict__ W1,
                         const float* __restrict__ b1,
                         float* __restrict__ out)
{
    __shared__ float hsh[NH];
    __shared__ float sv[N_TAG];
    const int w = blockIdx.x;
    const int n = threadIdx.x;

    for (int k = n; k < NH; k += N_TAG)
        hsh[k] = __uint_as_float((unsigned)g_hx[(size_t)w * NH + k]);
    __syncthreads();

    const float4* wr = (const float4*)(W1 + n * NH);
    float acc = b1[n];
#pragma unroll 8
    for (int k4 = 0; k4 < NH / 4; k4++) {
        float4 v = wr[k4];
        acc += v.x * hsh[k4 * 4]     + v.y * hsh[k4 * 4 + 1]
             + v.z * hsh[k4 * 4 + 2] + v.w * hsh[k4 * 4 + 3];
    }
    sv[n] = acc;
    __syncthreads();
    float mx = -1e30f;
    for (int i = 0; i < N_TAG; i++) mx = fmaxf(mx, sv[i]);
    float se = 0.f;
    for (int i = 0; i < N_TAG; i++) se += expf(sv[i] - mx);
    out[w * N_TAG + n] = acc - mx - logf(se);
}

// ---------------- launch ----------------
extern "C" void kernel_launch(void* const* d_in, const int* in_sizes, int n_in,
                              void* d_out, int out_size)
{
    const float* char_emb = (const float*)d_in[0];
    const float* char_Wih = (const float*)d_in[1];
    const float* char_Whh = (const float*)d_in[2];
    const float* char_bih = (const float*)d_in[3];
    const float* char_bhh = (const float*)d_in[4];
    const float* word_emb = (const float*)d_in[5];
    const float* Wih      = (const float*)d_in[6];
    const float* Whh      = (const float*)d_in[7];
    const float* bih      = (const float*)d_in[8];
    const float* bhh      = (const float*)d_in[9];
    const float* W1       = (const float*)d_in[10];
    const float* b1       = (const float*)d_in[11];
    const int*   x        = (const int*)d_in[12];
    const int*   chars    = (const int*)d_in[13];
    const int*   lens     = (const int*)d_in[14];
    float* out = (float*)d_out;

    k_init<<<1024, 256>>>();
    for (int t = 0; t < LC; t++)
        k_char_step<<<dim3(64, 8), 256>>>(char_emb, char_Wih, char_Whh,
                                          char_bih, char_bhh, chars, lens, t);
    k_gin<<<dim3(64, 32), 256>>>(word_emb, Wih, bih, bhh, x);
    k_word<<<NB_WORD, 288>>>(Whh);
    k_logits<<<S_LEN, N_TAG>>>(W1, b1, out);
}